// round 1
// baseline (speedup 1.0000x reference)
#include <cuda_runtime.h>
#include <cstdint>

#define NN 40000
#define EE 640000

// ---------------- device scratch (no allocations allowed) ----------------
__device__ float g_h[(size_t)NN * 160];    // per node: h_s[64] ++ h_v[32*3]
__device__ float g_agg[(size_t)NN * 480];  // per node: agg_s[96] ++ agg_v[128*3]

// ---------------- constants ----------------
__device__ __constant__ float kINV8       = 0.125f;
static constexpr float INV8        = 0.125f;
static constexpr float INV_SQRT32  = 0.17677669529663687f;
static constexpr float INV_SQRT3   = 0.57735026918962576f;
static constexpr float INV_SQRT2   = 0.70710678118654752f;
static constexpr float INV_SQRT96  = 0.10206207261596575f;
static constexpr float INV_SQRT128 = 0.08838834764831845f;
static constexpr float INV_NN      = 0.25f;   // 1/sqrt(16)

__device__ __forceinline__ float sigmoidf_(float x) { return 1.f / (1.f + __expf(-x)); }
__device__ __forceinline__ float siluf_(float x)    { return x / (1.f + __expf(-x)); }

// ---------------- zero accumulator ----------------
__global__ void zero_kernel() {
    size_t i = (size_t)blockIdx.x * blockDim.x + threadIdx.x;
    size_t total = (size_t)NN * 480 / 4;
    float4* p = reinterpret_cast<float4*>(g_agg);
    if (i < total) p[i] = make_float4(0.f, 0.f, 0.f, 0.f);
}

// ---------------- node pre: h = [s@lin1_ws, v@lin1_wv] ----------------
// persistent: 148 blocks x 320 threads; 16 nodes per chunk; thread = (col u in 0..159, q in {0,1})
// each thread computes its column for 8 nodes -> weight LDS reused 8x.
__global__ void __launch_bounds__(320) node_pre_kernel(
    const float* __restrict__ nf, const float* __restrict__ na,
    const float* __restrict__ lin1_ws, const float* __restrict__ lin1_wv)
{
    __shared__ float ws[64 * 64];
    __shared__ float wv[32 * 32];
    __shared__ float sv[16 * 160];
    __shared__ float aa[16];
    int t = threadIdx.x;
    for (int i = t; i < 4096; i += 320) ws[i] = lin1_ws[i];
    for (int i = t; i < 1024; i += 320) wv[i] = lin1_wv[i];
    int u = t % 160;
    int q = t / 160;

    for (int chunk = blockIdx.x; chunk < NN / 16; chunk += gridDim.x) {
        int nbase = chunk * 16;
        __syncthreads();
        for (int i = t; i < 16 * 160; i += 320) sv[i] = nf[(size_t)nbase * 160 + i];
        if (t < 16) aa[t] = na[nbase + t];
        __syncthreads();

        if (u < 64) {
            float acc[8];
            #pragma unroll
            for (int k = 0; k < 8; k++) acc[k] = 0.f;
            #pragma unroll
            for (int c = 0; c < 64; c++) {
                float w = ws[c * 64 + u];
                #pragma unroll
                for (int k = 0; k < 8; k++) acc[k] = fmaf(sv[(q * 8 + k) * 160 + c], w, acc[k]);
            }
            #pragma unroll
            for (int k = 0; k < 8; k++) {
                int n = q * 8 + k;
                g_h[(size_t)(nbase + n) * 160 + u] = acc[k] * aa[n] * INV8;
            }
        } else {
            int g = u - 64, d = g / 3, ii = g - d * 3;
            float acc[8];
            #pragma unroll
            for (int k = 0; k < 8; k++) acc[k] = 0.f;
            #pragma unroll
            for (int c = 0; c < 32; c++) {
                float w = wv[c * 32 + d];
                #pragma unroll
                for (int k = 0; k < 8; k++) acc[k] = fmaf(sv[(q * 8 + k) * 160 + 64 + c * 3 + ii], w, acc[k]);
            }
            #pragma unroll
            for (int k = 0; k < 8; k++) {
                int n = q * 8 + k;
                g_h[(size_t)(nbase + n) * 160 + u] = acc[k] * aa[n] * INV_SQRT32;
            }
        }
    }
}

// ---------------- edge kernel: MLP + messages + scatter ----------------
// persistent: 148 blocks x 512 threads, 64 edges per tile, 206KB smem.
#define ESMEM_FLOATS 51584
#define ESMEM_BYTES  (ESMEM_FLOATS * 4)

__global__ void __launch_bounds__(512) edge_kernel(
    const float* __restrict__ edge_scalars, const int* __restrict__ edge_src,
    const int* __restrict__ edge_dst, const float* __restrict__ edge_attr,
    const float* __restrict__ fc_w1, const float* __restrict__ fc_w2)
{
    extern __shared__ float sm[];
    float* w1s    = sm;            //  4096 : fc_w1 (64x64)
    float* w2s    = sm + 4096;     // 14336 : fc_w2 (64x224)
    float* es_sm  = sm + 18432;    //  4096 : edge_scalars tile (64x64)
    float* hid_sm = sm + 22528;    //  4096 : hidden (64x64)
    float* w_sm   = sm + 26624;    // 14336 : per-edge weights (64x224), scales folded
    float* hsv_sm = sm + 40960;    // 10240 : gathered h rows (64x160)
    float* ea_sm  = sm + 51200;    //   256 : edge_attr (64x4)
    int*   src_sm = (int*)(sm + 51456);   // 64
    int*   dst_sm = src_sm + 64;          // 64

    int t = threadIdx.x;
    for (int i = t; i < 4096;  i += 512) w1s[i] = fc_w1[i];
    for (int i = t; i < 14336; i += 512) w2s[i] = fc_w2[i];

    for (int tile = blockIdx.x; tile < EE / 64; tile += gridDim.x) {
        int base = tile * 64;
        __syncthreads();   // protect smem reuse from previous tile's message phase

        // ---- phase 0: stage edge data ----
        {
            const float4* s4 = reinterpret_cast<const float4*>(edge_scalars + (size_t)base * 64);
            float4* d4 = reinterpret_cast<float4*>(es_sm);
            for (int i = t; i < 1024; i += 512) d4[i] = s4[i];
            if (t < 64) {
                src_sm[t] = edge_src[base + t];
                dst_sm[t] = edge_dst[base + t];
                float4 ea = reinterpret_cast<const float4*>(edge_attr)[base + t];
                ea_sm[t * 4 + 0] = ea.x; ea_sm[t * 4 + 1] = ea.y;
                ea_sm[t * 4 + 2] = ea.z; ea_sm[t * 4 + 3] = ea.w;
            }
        }
        __syncthreads();

        // ---- phase 1: gather h rows (L2 resident) + hidden layer ----
        for (int i = t; i < 64 * 160; i += 512) {
            int e = i / 160, c = i - e * 160;
            hsv_sm[i] = g_h[(size_t)src_sm[e] * 160 + c];
        }
        {
            // thread -> (edge pair p in 0..31, col quad jq in 0..15): 2x4 register tile
            int p = t >> 4, jq = t & 15;
            const float* er0 = es_sm + (2 * p) * 64;
            const float* er1 = er0 + 64;
            float a0x = 0, a0y = 0, a0z = 0, a0w = 0;
            float a1x = 0, a1y = 0, a1z = 0, a1w = 0;
            #pragma unroll
            for (int c = 0; c < 64; c++) {
                float4 w = *reinterpret_cast<const float4*>(w1s + c * 64 + jq * 4);
                float x0 = er0[c], x1 = er1[c];
                a0x = fmaf(x0, w.x, a0x); a0y = fmaf(x0, w.y, a0y);
                a0z = fmaf(x0, w.z, a0z); a0w = fmaf(x0, w.w, a0w);
                a1x = fmaf(x1, w.x, a1x); a1y = fmaf(x1, w.y, a1y);
                a1z = fmaf(x1, w.z, a1z); a1w = fmaf(x1, w.w, a1w);
            }
            float* h0 = hid_sm + (2 * p) * 64 + jq * 4;
            h0[0] = siluf_(a0x * INV8); h0[1] = siluf_(a0y * INV8);
            h0[2] = siluf_(a0z * INV8); h0[3] = siluf_(a0w * INV8);
            float* h1 = h0 + 64;
            h1[0] = siluf_(a1x * INV8); h1[1] = siluf_(a1y * INV8);
            h1[2] = siluf_(a1z * INV8); h1[3] = siluf_(a1w * INV8);
        }
        __syncthreads();

        // ---- phase 2: w = hid @ fc_w2 (scales folded into w4/w5) ----
        for (int uu = t; uu < 1792; uu += 512) {        // 32 edge-pairs x 56 col-quads
            int p = uu / 56, jq = uu - p * 56;
            const float* h0 = hid_sm + (2 * p) * 64;
            const float* h1 = h0 + 64;
            float a0x = 0, a0y = 0, a0z = 0, a0w = 0;
            float a1x = 0, a1y = 0, a1z = 0, a1w = 0;
            #pragma unroll
            for (int c = 0; c < 64; c++) {
                float4 w = *reinterpret_cast<const float4*>(w2s + c * 224 + jq * 4);
                float x0 = h0[c], x1 = h1[c];
                a0x = fmaf(x0, w.x, a0x); a0y = fmaf(x0, w.y, a0y);
                a0z = fmaf(x0, w.z, a0z); a0w = fmaf(x0, w.w, a0w);
                a1x = fmaf(x1, w.x, a1x); a1y = fmaf(x1, w.y, a1y);
                a1z = fmaf(x1, w.z, a1z); a1w = fmaf(x1, w.w, a1w);
            }
            int j = jq * 4;
            float sc0, sc1, sc2, sc3;
            {
                // fold: /8 everywhere; * 1/sqrt(3) for w4 (cols 160..191); * 1/sqrt(2) for w5 (192..223)
                auto scl = [](int jj) {
                    float s = INV8;
                    if (jj >= 192) s *= INV_SQRT2;
                    else if (jj >= 160) s *= INV_SQRT3;
                    return s;
                };
                sc0 = scl(j + 0); sc1 = scl(j + 1); sc2 = scl(j + 2); sc3 = scl(j + 3);
            }
            float* o0 = w_sm + (2 * p) * 224 + j;
            o0[0] = a0x * sc0; o0[1] = a0y * sc1; o0[2] = a0z * sc2; o0[3] = a0w * sc3;
            float* o1 = o0 + 224;
            o1[0] = a1x * sc0; o1[1] = a1y * sc1; o1[2] = a1z * sc2; o1[3] = a1w * sc3;
        }
        __syncthreads();

        // ---- phase 3: messages + float4 scatter-add ----
        // per edge 480 components laid out exactly as agg row: [m_s1(64) m_s2(32) m_v1(192) m_v2(96) m_v3(96)]
        for (int i = t; i < 64 * 120; i += 512) {
            int e = i / 120, q = i - e * 120;
            int f = q * 4;
            const float* W = w_sm + e * 224;
            const float* H = hsv_sm + e * 160;
            float e0 = ea_sm[e * 4 + 0];
            float b0 = ea_sm[e * 4 + 1], b1 = ea_sm[e * 4 + 2], b2 = ea_sm[e * 4 + 3];
            float v[4];
            if (f < 64) {                               // m_s1 = w1 * es * e0
                #pragma unroll
                for (int u2 = 0; u2 < 4; u2++) v[u2] = W[f + u2] * H[f + u2] * e0;
            } else if (f < 96) {                        // m_s2 = w4 * (ev . e1)   (1/sqrt3 folded)
                #pragma unroll
                for (int u2 = 0; u2 < 4; u2++) {
                    int c = f + u2 - 64;
                    const float* a = H + 64 + c * 3;
                    v[u2] = W[160 + c] * (a[0] * b0 + a[1] * b1 + a[2] * b2);
                }
            } else if (f < 288) {                       // m_v1 = (w2*es) outer e1
                #pragma unroll
                for (int u2 = 0; u2 < 4; u2++) {
                    int g = f + u2 - 96; int d = g / 3; int ii = g - d * 3;
                    float bb = (ii == 0) ? b0 : ((ii == 1) ? b1 : b2);
                    v[u2] = W[64 + d] * H[d] * bb;
                }
            } else if (f < 384) {                       // m_v2 = w3 * ev * e0
                #pragma unroll
                for (int u2 = 0; u2 < 4; u2++) {
                    int g = f + u2 - 288; int c = g / 3;
                    v[u2] = W[128 + c] * H[64 + g] * e0;
                }
            } else {                                    // m_v3 = w5 * cross(ev, e1)  (1/sqrt2 folded)
                #pragma unroll
                for (int u2 = 0; u2 < 4; u2++) {
                    int g = f + u2 - 384; int c = g / 3; int ii = g - c * 3;
                    const float* a = H + 64 + c * 3;
                    float cr;
                    if (ii == 0)      cr = a[1] * b2 - a[2] * b1;
                    else if (ii == 1) cr = a[2] * b0 - a[0] * b2;
                    else              cr = a[0] * b1 - a[1] * b0;
                    v[u2] = W[192 + c] * cr;
                }
            }
            float4* addr = reinterpret_cast<float4*>(g_agg + (size_t)dst_sm[e] * 480 + f);
            atomicAdd(addr, make_float4(v[0], v[1], v[2], v[3]));   // sm_90+ vector RED
        }
    }
}

// ---------------- node post: lin2 + self-connection + gating ----------------
// persistent: 148 blocks x 384 threads; 16 nodes per chunk; thread = (unit u in 0..191, q in {0,1})
// u<96  -> pre_s column (8 nodes);  u>=96 -> pre_v component (8 nodes)
#define PSMEM_FLOATS 31248
#define PSMEM_BYTES  (PSMEM_FLOATS * 4)

__global__ void __launch_bounds__(384) node_post_kernel(
    const float* __restrict__ nf, const float* __restrict__ na,
    const float* __restrict__ sc_ws, const float* __restrict__ sc_wv,
    const float* __restrict__ lin2_ws, const float* __restrict__ lin2_wv,
    float* __restrict__ out)
{
    extern __shared__ float sm[];
    float* scws  = sm;              //  6144 (64x96)
    float* l2ws  = sm + 6144;       //  9216 (96x96)
    float* scwv  = sm + 15360;      //  1024 (32x32)
    float* l2wv  = sm + 16384;      //  4096 (128x32)
    float* sv    = sm + 20480;      //  2560 (16x160)
    float* ag    = sm + 23040;      //  7680 (16x480)
    float* gates = sm + 30720;      //   512 (16x32)
    float* aa    = sm + 31232;      //    16

    int t = threadIdx.x;
    for (int i = t; i < 6144; i += 384) scws[i] = sc_ws[i];
    for (int i = t; i < 9216; i += 384) l2ws[i] = lin2_ws[i];
    for (int i = t; i < 1024; i += 384) scwv[i] = sc_wv[i];
    for (int i = t; i < 4096; i += 384) l2wv[i] = lin2_wv[i];
    int u = t % 192, q = t / 192;

    for (int chunk = blockIdx.x; chunk < NN / 16; chunk += gridDim.x) {
        int nbase = chunk * 16;
        __syncthreads();   // protect staging + gates reuse
        for (int i = t; i < 2560; i += 384) sv[i] = nf[(size_t)nbase * 160 + i];
        for (int i = t; i < 7680; i += 384) ag[i] = g_agg[(size_t)nbase * 480 + i];
        if (t < 16) aa[t] = na[nbase + t];
        __syncthreads();

        float pv[8];
        bool is_vec = (u >= 96);
        if (!is_vec) {
            int d = u;
            float acc[8], ac2[8];
            #pragma unroll
            for (int k = 0; k < 8; k++) { acc[k] = 0.f; ac2[k] = 0.f; }
            #pragma unroll
            for (int c = 0; c < 64; c++) {
                float w = scws[c * 96 + d];
                #pragma unroll
                for (int k = 0; k < 8; k++) acc[k] = fmaf(sv[(q * 8 + k) * 160 + c], w, acc[k]);
            }
            #pragma unroll
            for (int c = 0; c < 96; c++) {
                float w = l2ws[c * 96 + d];
                #pragma unroll
                for (int k = 0; k < 8; k++) ac2[k] = fmaf(ag[(q * 8 + k) * 480 + c], w, ac2[k]);
            }
            #pragma unroll
            for (int k = 0; k < 8; k++) {
                int n = q * 8 + k;
                float pre = (acc[k] * INV8 + ac2[k] * (INV_SQRT96 * INV_NN)) * aa[n];
                if (d < 64) out[(size_t)(nbase + n) * 160 + d] = siluf_(pre);
                else        gates[n * 32 + (d - 64)] = sigmoidf_(pre);
            }
        } else {
            int g = u - 96, d = g / 3, ii = g - d * 3;
            float acc[8], ac2[8];
            #pragma unroll
            for (int k = 0; k < 8; k++) { acc[k] = 0.f; ac2[k] = 0.f; }
            #pragma unroll
            for (int c = 0; c < 32; c++) {
                float w = scwv[c * 32 + d];
                #pragma unroll
                for (int k = 0; k < 8; k++) acc[k] = fmaf(sv[(q * 8 + k) * 160 + 64 + c * 3 + ii], w, acc[k]);
            }
            #pragma unroll
            for (int c = 0; c < 128; c++) {
                float w = l2wv[c * 32 + d];
                #pragma unroll
                for (int k = 0; k < 8; k++) ac2[k] = fmaf(ag[(q * 8 + k) * 480 + 96 + c * 3 + ii], w, ac2[k]);
            }
            #pragma unroll
            for (int k = 0; k < 8; k++) {
                int n = q * 8 + k;
                pv[k] = (acc[k] * INV_SQRT32 + ac2[k] * (INV_SQRT128 * INV_NN)) * aa[n];
            }
        }
        __syncthreads();   // gates visible to vector threads
        if (is_vec) {
            int g = u - 96, d = g / 3;
            #pragma unroll
            for (int k = 0; k < 8; k++) {
                int n = q * 8 + k;
                out[(size_t)(nbase + n) * 160 + 64 + g] = gates[n * 32 + d] * pv[k];
            }
        }
    }
}

// ---------------- launch ----------------
extern "C" void kernel_launch(void* const* d_in, const int* in_sizes, int n_in,
                              void* d_out, int out_size)
{
    const float* nf      = (const float*)d_in[0];
    const float* na      = (const float*)d_in[1];
    const int*   esrc    = (const int*)  d_in[2];
    const int*   edst    = (const int*)  d_in[3];
    const float* eattr   = (const float*)d_in[4];
    const float* escal   = (const float*)d_in[5];
    const float* lin1_ws = (const float*)d_in[6];
    const float* lin1_wv = (const float*)d_in[7];
    const float* fc_w1   = (const float*)d_in[8];
    const float* fc_w2   = (const float*)d_in[9];
    const float* sc_ws   = (const float*)d_in[10];
    const float* sc_wv   = (const float*)d_in[11];
    const float* lin2_ws = (const float*)d_in[12];
    const float* lin2_wv = (const float*)d_in[13];
    float* out = (float*)d_out;

    cudaFuncSetAttribute(edge_kernel,      cudaFuncAttributeMaxDynamicSharedMemorySize, ESMEM_BYTES);
    cudaFuncSetAttribute(node_post_kernel, cudaFuncAttributeMaxDynamicSharedMemorySize, PSMEM_BYTES);

    zero_kernel<<<(NN * 480 / 4 + 255) / 256, 256>>>();
    node_pre_kernel<<<148, 320>>>(nf, na, lin1_ws, lin1_wv);
    edge_kernel<<<148, 512, ESMEM_BYTES>>>(escal, esrc, edst, eattr, fc_w1, fc_w2);
    node_post_kernel<<<148, 384, PSMEM_BYTES>>>(nf, na, sc_ws, sc_wv, lin2_ws, lin2_wv, out);
}